// round 3
// baseline (speedup 1.0000x reference)
#include <cuda_runtime.h>
#include <math.h>

#define NB 16384
#define ND 16
#define KNN 25
#define LAMBDA_TSA 0.1f

// ---------------- device scratch (no allocations allowed) ----------------
__device__ float g_sq[NB];
__device__ int   g_nbrs[NB][KNN];
__device__ float g_acc_recon;
__device__ float g_acc_tsa;

// ---------------- kernel 1: squared norms + zero accumulators ----------------
__global__ void k_setup(const float* __restrict__ raw) {
    int i = blockIdx.x * blockDim.x + threadIdx.x;
    if (i < NB) {
        const float4* r4 = reinterpret_cast<const float4*>(raw + (size_t)i * ND);
        float s = 0.f;
#pragma unroll
        for (int j = 0; j < 4; ++j) {
            float4 v = r4[j];
            s = fmaf(v.x, v.x, s); s = fmaf(v.y, v.y, s);
            s = fmaf(v.z, v.z, s); s = fmaf(v.w, v.w, s);
        }
        g_sq[i] = s;
    }
    if (i == 0) { g_acc_recon = 0.f; g_acc_tsa = 0.f; }
}

// ---------------- kernel 2: recon MSE sum ----------------
__global__ void k_recon(const float* __restrict__ o, const float* __restrict__ t) {
    const float4* o4 = reinterpret_cast<const float4*>(o);
    const float4* t4 = reinterpret_cast<const float4*>(t);
    const int n4 = NB * ND / 4;
    float s = 0.f;
    for (int idx = blockIdx.x * blockDim.x + threadIdx.x; idx < n4;
         idx += gridDim.x * blockDim.x) {
        float4 a = o4[idx], b = t4[idx];
        float dx = a.x - b.x, dy = a.y - b.y, dz = a.z - b.z, dw = a.w - b.w;
        s = fmaf(dx, dx, s); s = fmaf(dy, dy, s);
        s = fmaf(dz, dz, s); s = fmaf(dw, dw, s);
    }
#pragma unroll
    for (int off = 16; off; off >>= 1) s += __shfl_xor_sync(0xffffffffu, s, off);
    __shared__ float ws[8];
    int lane = threadIdx.x & 31, wid = threadIdx.x >> 5;
    if (lane == 0) ws[wid] = s;
    __syncthreads();
    if (threadIdx.x == 0) {
        float tot = 0.f;
#pragma unroll
        for (int k = 0; k < 8; ++k) tot += ws[k];
        atomicAdd(&g_acc_recon, tot);
    }
}

// ---------------- top-k insert (register resident) ----------------
__device__ __forceinline__ void topk_insert(float (&bd)[KNN], int (&bi)[KNN],
                                            float& worst, float d2, int cg) {
    if (d2 < worst) {
        bool done = false;
#pragma unroll
        for (int kk = 0; kk < KNN; ++kk) {
            if (!done && bd[kk] == worst) { bd[kk] = d2; bi[kk] = cg; done = true; }
        }
        float w = -3.402823466e+38f;
#pragma unroll
        for (int kk = 0; kk < KNN; ++kk) w = fmaxf(w, bd[kk]);
        worst = w;
    }
}

// ---------------- kernel 3: exact KNN (tiled distance GEMM + fused top-k) ----
// grid = 128 blocks (128 queries each), 256 threads, all-static smem (<48KB).
// Candidate tiles of 64; per-thread 8x4 register micro-tile.
__global__ void __launch_bounds__(256) k_knn(const float* __restrict__ raw) {
    __shared__ float Qs[16 * 128];     // d-major query tile
    __shared__ float Cs[16 * 64];      // d-major candidate tile
    __shared__ float sqC[64];
    __shared__ float Dist[128 * 65];   // padded distance staging

    const int tid   = threadIdx.x;
    const int qbase = blockIdx.x * 128;
    const float4* raw4 = reinterpret_cast<const float4*>(raw);

    // load & transpose query tile (coalesced float4 reads)
    for (int f = tid; f < 512; f += 256) {
        int q = f >> 2, dc = f & 3;
        float4 v = raw4[(size_t)(qbase + q) * 4 + dc];
        Qs[(dc * 4 + 0) * 128 + q] = v.x;
        Qs[(dc * 4 + 1) * 128 + q] = v.y;
        Qs[(dc * 4 + 2) * 128 + q] = v.z;
        Qs[(dc * 4 + 3) * 128 + q] = v.w;
    }

    // per-thread top-k state (thread t<128: query t, candidates [0,32);
    //                         thread t>=128: query t-128, candidates [32,64))
    float bd[KNN];
    int   bi[KNN];
#pragma unroll
    for (int k = 0; k < KNN; ++k) { bd[k] = 3.402823466e+38f; bi[k] = 0; }
    float worst = 3.402823466e+38f;
    const int myq   = tid & 127;
    const int qglob = qbase + myq;
    const int clo   = (tid >> 7) * 32;

    const int r = tid >> 4, cl = tid & 15;
    const int q0 = r * 8, c0 = cl * 4;

    for (int tile = 0; tile < NB / 64; ++tile) {
        const int cbase = tile * 64;
        __syncthreads();  // previous top-k reads of Dist/Cs complete

        // load & transpose candidate tile (64 pts x 4 float4 = 256 loads)
        {
            int c = tid >> 2, dc = tid & 3;
            float4 v = raw4[(size_t)(cbase + c) * 4 + dc];
            Cs[(dc * 4 + 0) * 64 + c] = v.x;
            Cs[(dc * 4 + 1) * 64 + c] = v.y;
            Cs[(dc * 4 + 2) * 64 + c] = v.z;
            Cs[(dc * 4 + 3) * 64 + c] = v.w;
        }
        if (tid < 64) sqC[tid] = g_sq[cbase + tid];
        __syncthreads();

        // 128x64 distance tile: acc = dot(q,c); d2' = sq_c - 2*acc
        float acc[8][4];
#pragma unroll
        for (int i = 0; i < 8; ++i)
#pragma unroll
            for (int j = 0; j < 4; ++j) acc[i][j] = 0.f;

#pragma unroll
        for (int d = 0; d < 16; ++d) {
            float4 qa = *reinterpret_cast<const float4*>(Qs + d * 128 + q0);
            float4 qb = *reinterpret_cast<const float4*>(Qs + d * 128 + q0 + 4);
            float4 ca = *reinterpret_cast<const float4*>(Cs + d * 64 + c0);
            float qv[8] = {qa.x, qa.y, qa.z, qa.w, qb.x, qb.y, qb.z, qb.w};
            float cv[4] = {ca.x, ca.y, ca.z, ca.w};
#pragma unroll
            for (int i = 0; i < 8; ++i)
#pragma unroll
                for (int j = 0; j < 4; ++j) acc[i][j] = fmaf(qv[i], cv[j], acc[i][j]);
        }
        float sc[4];
#pragma unroll
        for (int j = 0; j < 4; ++j) sc[j] = sqC[c0 + j];
#pragma unroll
        for (int i = 0; i < 8; ++i)
#pragma unroll
            for (int j = 0; j < 4; ++j)
                Dist[(q0 + i) * 65 + (c0 + j)] = fmaf(-2.f, acc[i][j], sc[j]);
        __syncthreads();

        // top-k scan (each thread: 32 candidates of its query; warp-conflict-free)
        const float* drow = Dist + myq * 65;
#pragma unroll 4
        for (int c = clo; c < clo + 32; ++c) {
            float d2 = drow[c];
            int cg = cbase + c;
            if (cg != qglob) topk_insert(bd, bi, worst, d2, cg);
        }
    }

    // merge the two half-lists per query (stage via Dist)
    __syncthreads();
    float* mf = Dist;                               // 128*25 floats
    int*   mi = reinterpret_cast<int*>(Dist + 128 * KNN);
    if (tid >= 128) {
        int q = tid - 128;
#pragma unroll
        for (int k = 0; k < KNN; ++k) { mf[q * KNN + k] = bd[k]; mi[q * KNN + k] = bi[k]; }
    }
    __syncthreads();
    if (tid < 128) {
#pragma unroll
        for (int k = 0; k < KNN; ++k)
            topk_insert(bd, bi, worst, mf[tid * KNN + k], mi[tid * KNN + k]);
#pragma unroll
        for (int k = 0; k < KNN; ++k) g_nbrs[qbase + tid][k] = bi[k];
    }
}

// ---------------- kernel 4: per-point TSA term (warp per point) --------------
// P=1: sum((Pz-Px)^2) = 2 - 2*(u.v)^2 with u,v unit top-eigenvectors.
// Top eigenvector of 16x16 cov via 8 repeated squarings (A^256).
#define TSA_WPB 8
__global__ void __launch_bounds__(256) k_tsa(const float* __restrict__ latent,
                                             const float* __restrict__ raw) {
    __shared__ float s_pts[TSA_WPB][KNN][ND];
    __shared__ float s_A[TSA_WPB][16 * 17];
    __shared__ float s_B[TSA_WPB][16 * 17];
    __shared__ float s_u[TSA_WPB][16];
    __shared__ float s_v[TSA_WPB][16];
    __shared__ float s_mu[TSA_WPB][16];
    __shared__ int   s_nb[TSA_WPB][KNN];

    const int w = threadIdx.x >> 5, lane = threadIdx.x & 31;
    const int i = blockIdx.x * TSA_WPB + w;

    if (lane < KNN) s_nb[w][lane] = g_nbrs[i][lane];
    __syncwarp();

    for (int p = 0; p < 2; ++p) {
        const float* src = p ? raw : latent;
        float* uvec = p ? s_v[w] : s_u[w];

        // gather neighbor rows
        for (int idx = lane; idx < KNN * ND; idx += 32) {
            int k = idx >> 4, d = idx & 15;
            s_pts[w][k][d] = src[(size_t)s_nb[w][k] * ND + d];
        }
        __syncwarp();
        // column means
        if (lane < 16) {
            float m = 0.f;
#pragma unroll
            for (int k = 0; k < KNN; ++k) m += s_pts[w][k][lane];
            s_mu[w][lane] = m * (1.f / KNN);
        }
        __syncwarp();
        for (int idx = lane; idx < KNN * ND; idx += 32) {
            int k = idx >> 4, d = idx & 15;
            s_pts[w][k][d] -= s_mu[w][d];
        }
        __syncwarp();
        // covariance (unnormalized: eigvec scale-invariant)
        for (int e = lane; e < 256; e += 32) {
            int a = e >> 4, b = e & 15;
            float s = 0.f;
#pragma unroll
            for (int k = 0; k < KNN; ++k) s = fmaf(s_pts[w][k][a], s_pts[w][k][b], s);
            s_A[w][a * 17 + b] = s;
        }
        __syncwarp();

        // 8 repeated squarings with max-diag normalization
        float* Ain = s_A[w];
        float* Aou = s_B[w];
#pragma unroll 1
        for (int sq = 0; sq < 8; ++sq) {
            for (int e = lane; e < 256; e += 32) {
                int a = e >> 4, b = e & 15;
                float s = 0.f;
#pragma unroll
                for (int k = 0; k < 16; ++k) s = fmaf(Ain[a * 17 + k], Ain[k * 17 + b], s);
                Aou[a * 17 + b] = s;
            }
            __syncwarp();
            float dv = (lane < 16) ? Aou[lane * 17 + lane] : 0.f;
#pragma unroll
            for (int off = 16; off; off >>= 1)
                dv = fmaxf(dv, __shfl_xor_sync(0xffffffffu, dv, off));
            float inv = 1.f / dv;
            for (int e = lane; e < 256; e += 32) {
                int a = e >> 4, b = e & 15;
                Aou[a * 17 + b] *= inv;
            }
            __syncwarp();
            float* tmp = Ain; Ain = Aou; Aou = tmp;
        }

        // dominant eigenvector = largest-diag column of A^256, normalized
        float bv = (lane < 16) ? Ain[lane * 17 + lane] : -1.f;
        int   bx = (lane < 16) ? lane : 1000;
#pragma unroll
        for (int off = 16; off; off >>= 1) {
            float ov = __shfl_xor_sync(0xffffffffu, bv, off);
            int   oi = __shfl_xor_sync(0xffffffffu, bx, off);
            if (ov > bv || (ov == bv && oi < bx)) { bv = ov; bx = oi; }
        }
        float uv = (lane < 16) ? Ain[lane * 17 + bx] : 0.f;
        float ss = uv * uv;
#pragma unroll
        for (int off = 16; off; off >>= 1) ss += __shfl_xor_sync(0xffffffffu, ss, off);
        float rn = rsqrtf(ss);
        if (lane < 16) uvec[lane] = uv * rn;
        __syncwarp();
    }

    float pd = (lane < 16) ? s_u[w][lane] * s_v[w][lane] : 0.f;
#pragma unroll
    for (int off = 16; off; off >>= 1) pd += __shfl_xor_sync(0xffffffffu, pd, off);
    if (lane == 0) {
        float term = fmaf(-2.f * pd, pd, 2.f);
        atomicAdd(&g_acc_tsa, term);
    }
}

// ---------------- kernel 5: finalize ----------------
__global__ void k_final(float* __restrict__ out) {
    out[0] = g_acc_recon * (1.f / (NB * ND)) + LAMBDA_TSA * g_acc_tsa * (1.f / NB);
}

// ---------------- launcher (kernel launches only; graph-capturable) ----------
extern "C" void kernel_launch(void* const* d_in, const int* in_sizes, int n_in,
                              void* d_out, int out_size) {
    const float* outputs = (const float*)d_in[0];
    const float* targets = (const float*)d_in[1];
    const float* latent  = (const float*)d_in[2];
    const float* raw     = (const float*)d_in[3];
    float* out = (float*)d_out;

    k_setup<<<NB / 256, 256>>>(raw);
    k_recon<<<64, 256>>>(outputs, targets);
    k_knn<<<NB / 128, 256>>>(raw);
    k_tsa<<<NB / TSA_WPB, 256>>>(latent, raw);
    k_final<<<1, 1>>>(out);
}